// round 4
// baseline (speedup 1.0000x reference)
#include <cuda_runtime.h>
#include <math.h>

#define SEQ_T 256
#define NB    64
#define DIM   512
#define TBM   (SEQ_T * NB * DIM)   /* 8388608 */

// ---------------- scratch (static device memory; no runtime alloc) ----------
__device__ float g_iouT[(size_t)SEQ_T * 4 * DIM * NB];  // [t][gate][m][b]
__device__ float g_ctxT[(size_t)SEQ_T * DIM * NB];      // [t][m][b]
__device__ float g_wcsT[(size_t)SEQ_T * DIM * NB];      // [t][m][b]  (tanh applied)
__device__ float g_hT  [(size_t)SEQ_T * DIM * NB];      // [t][m][b]  h history (transposed)
__device__ float g_h0T [DIM * NB];                      // [m][b]
__device__ float g_cT  [DIM * NB];                      // [m][b]
__device__ unsigned g_flags[128 * 32];                  // per-block epoch, 128B apart

typedef unsigned long long ull;

__device__ __forceinline__ void ffma2(ull& d, ull a, ull b) {
    asm("fma.rn.f32x2 %0, %1, %2, %0;" : "+l"(d) : "l"(a), "l"(b));
}
__device__ __forceinline__ ull packdup(float a) {
    ull r; asm("mov.b64 %0, {%1, %1};" : "=l"(r) : "f"(a)); return r;
}
__device__ __forceinline__ float tanh_fast(float x) {
    float y; asm("tanh.approx.f32 %0, %1;" : "=f"(y) : "f"(x)); return y;
}
__device__ __forceinline__ float sigmoid_fast(float x) {
    return fmaf(0.5f, tanh_fast(0.5f * x), 0.5f);
}
__device__ __forceinline__ unsigned ld_flag(const unsigned* p) {
    unsigned v;
    asm volatile("ld.global.cg.u32 %0, [%1];" : "=r"(v) : "l"(p));
    return v;
}
__device__ __forceinline__ void st_flag(unsigned* p, unsigned v) {
    asm volatile("st.global.cg.u32 [%0], %1;" :: "l"(p), "r"(v));
}

// ---------------------------------------------------------------------------
__global__ void init_kernel(const float* __restrict__ h0) {
    int b = blockIdx.x;          // 64 blocks
    int m = threadIdx.x;         // 512 threads
    g_h0T[m * NB + b] = h0[b * DIM + m];
    int idx = b * 512 + m;
    if (idx < 128 * 32) g_flags[idx] = 0u;
}

// ---------------------------------------------------------------------------
// fp32 SGEMM with packed FFMA2: C = A * B^T + bias (+tanh), transposed stores.
// BM=BN=128, BK=16, 256 threads, 8x8 register tile (as 8x4 f32x2 pairs).
// ---------------------------------------------------------------------------
__global__ void __launch_bounds__(256) gemm_kernel(
    int mode,
    const float* __restrict__ A0, const float* __restrict__ A1,
    const float* __restrict__ B0, const float* __restrict__ B1,
    const float* __restrict__ bias0, const float* __restrict__ bias1,
    int N, int K)
{
    __shared__ float As[16 * 132];
    __shared__ float Bs[16 * 132];

    const int tid = threadIdx.x;
    const int bm  = blockIdx.y * 128;
    const int bn  = blockIdx.x * 128;
    const int tx  = tid & 15;
    const int ty  = tid >> 4;

    ull accP[8][4];
    #pragma unroll
    for (int i = 0; i < 8; i++)
        #pragma unroll
        for (int j = 0; j < 4; j++) accP[i][j] = 0ull;

    for (int k0 = 0; k0 < K; k0 += 16) {
        const float* Asrc; const float* Bsrc; int ko;
        if (k0 < 512) { Asrc = A0; Bsrc = B0; ko = k0; }
        else          { Asrc = A1; Bsrc = B1; ko = k0 - 512; }

        #pragma unroll
        for (int i = 0; i < 2; i++) {
            int l  = tid + i * 256;
            int r  = l >> 2;
            int c4 = (l & 3) * 4;
            float4 av = *reinterpret_cast<const float4*>(Asrc + (size_t)(bm + r) * 512 + ko + c4);
            As[(c4 + 0) * 132 + r] = av.x;
            As[(c4 + 1) * 132 + r] = av.y;
            As[(c4 + 2) * 132 + r] = av.z;
            As[(c4 + 3) * 132 + r] = av.w;
            float4 bv = *reinterpret_cast<const float4*>(Bsrc + (size_t)(bn + r) * 512 + ko + c4);
            Bs[(c4 + 0) * 132 + r] = bv.x;
            Bs[(c4 + 1) * 132 + r] = bv.y;
            Bs[(c4 + 2) * 132 + r] = bv.z;
            Bs[(c4 + 3) * 132 + r] = bv.w;
        }
        __syncthreads();

        #pragma unroll
        for (int kk = 0; kk < 16; kk++) {
            float a8[8];
            float4 b0 = *reinterpret_cast<const float4*>(&Bs[kk * 132 + tx * 8]);
            float4 b1 = *reinterpret_cast<const float4*>(&Bs[kk * 132 + tx * 8 + 4]);
            *reinterpret_cast<float4*>(a8)     = *reinterpret_cast<const float4*>(&As[kk * 132 + ty * 8]);
            *reinterpret_cast<float4*>(a8 + 4) = *reinterpret_cast<const float4*>(&As[kk * 132 + ty * 8 + 4]);
            ull bp[4];
            bp[0] = reinterpret_cast<const ulonglong2*>(&b0)->x;
            bp[1] = reinterpret_cast<const ulonglong2*>(&b0)->y;
            bp[2] = reinterpret_cast<const ulonglong2*>(&b1)->x;
            bp[3] = reinterpret_cast<const ulonglong2*>(&b1)->y;
            #pragma unroll
            for (int i = 0; i < 8; i++) {
                ull ad = packdup(a8[i]);
                #pragma unroll
                for (int j = 0; j < 4; j++)
                    ffma2(accP[i][j], ad, bp[j]);
            }
        }
        __syncthreads();
    }

    const int col0 = bn + tx * 8;
    float bias[8];
    #pragma unroll
    for (int j = 0; j < 8; j++) {
        float v = bias0[col0 + j];
        if (bias1) v += bias1[col0 + j];
        bias[j] = v;
    }

    #pragma unroll
    for (int i = 0; i < 8; i++) {
        int row = bm + ty * 8 + i;
        int t   = row >> 6;
        int b   = row & 63;
        #pragma unroll
        for (int j = 0; j < 8; j++) {
            float2 pr = *reinterpret_cast<float2*>(&accP[i][j >> 1]);
            float v = ((j & 1) ? pr.y : pr.x) + bias[j];
            int col = col0 + j;
            if (mode == 0) {
                int g  = col >> 9;
                int mc = col & 511;
                g_iouT[(((size_t)t * 4 + g) * 512 + mc) * 64 + b] = v;
            } else if (mode == 1) {
                g_ctxT[(size_t)t * (512 * 64) + (size_t)col * 64 + b] = v;
            } else {
                g_wcsT[(size_t)t * (512 * 64) + (size_t)col * 64 + b] = tanhf(v);
            }
        }
    }
}

// ---------------------------------------------------------------------------
// Persistent weight-stationary scan with FFMA2 + distributed flag barrier.
// 128 blocks (co-resident), 256 threads. Weights duplicated (w,w) in ~80KB smem.
// warp = m_local(4) x bhalf(2); lane = kc(bits3-4) x bq(bits0-2).
// ---------------------------------------------------------------------------
#define W4TOT 16448                       /* floats: 4 m * (4 kc * 1028) */
#define SCAN_SMEM_FLOATS (W4TOT + 4 * 1032)
#define SCAN_SMEM_BYTES  (SCAN_SMEM_FLOATS * 4)

__global__ void __launch_bounds__(256) scan_kernel(
    const float* __restrict__ W_iouh, const float* __restrict__ b_iouh,
    const float* __restrict__ W_fh,   const float* __restrict__ b_fh,
    const float* __restrict__ c0)
{
    extern __shared__ float sm[];

    const int tid   = threadIdx.x;
    const int warp  = tid >> 5;
    const int lane  = tid & 31;
    const int m_l   = warp >> 1;
    const int bhalf = warp & 1;
    const int kc    = (lane >> 3) & 3;
    const int bq    = lane & 7;
    const int m     = blockIdx.x * 4 + m_l;
    const int b_own = bhalf * 32 + bq * 4 + kc;

    // ---- weights into smem, duplicated (w,w) pairs ----
    for (int idx = tid; idx < 8192; idx += 256) {
        int ml = idx >> 11;
        int r  = idx & 2047;
        int c  = r >> 9;
        int r2 = r & 511;
        int i  = r2 >> 2;
        int g  = r2 & 3;
        int mg = blockIdx.x * 4 + ml;
        float w = W_iouh[((size_t)g * 512 + mg) * 512 + c * 128 + i];
        float* p = sm + ml * 4112 + c * 1028 + i * 8 + g * 2;
        p[0] = w; p[1] = w;
    }
    for (int idx = tid; idx < 2048; idx += 256) {
        int ml = idx >> 9;
        int r  = idx & 511;
        int c  = r >> 7;
        int i  = r & 127;
        int mg = blockIdx.x * 4 + ml;
        float w = W_fh[(size_t)mg * 512 + c * 128 + i];
        float* p = sm + W4TOT + ml * 1032 + c * 258 + i * 2;
        p[0] = w; p[1] = w;
    }
    __syncthreads();

    const float bf  = b_iouh[m];
    const float bi  = b_iouh[512 + m];
    const float bo  = b_iouh[1024 + m];
    const float boc = b_iouh[1536 + m];
    const float bfh = b_fh[m];

    float c_reg = c0[(size_t)b_own * 512 + m];

    const float4* w4f = reinterpret_cast<const float4*>(sm + m_l * 4112 + kc * 1028);
    const float2* w1f = reinterpret_cast<const float2*>(sm + W4TOT + m_l * 1032 + kc * 258);
    const int hoff = kc * 2048 + bhalf * 8 + bq;   // float4 index within step slice
    const unsigned* myflag = &g_flags[tid * 32];   // tid<128 poll targets

    for (int t = 0; t < SEQ_T; t++) {
        // addend loads first (independent of h_{t-1}); latency hides under the wait
        const size_t ib = (((size_t)t * 4) * 512 + m) * 64 + b_own;
        const size_t sb = (size_t)t * (512 * 64) + (size_t)m * 64 + b_own;
        float af  = __ldg(&g_iouT[ib]);
        float ai  = __ldg(&g_iouT[ib + 1 * 512 * 64]);
        float ao  = __ldg(&g_iouT[ib + 2 * 512 * 64]);
        float aoc = __ldg(&g_iouT[ib + 3 * 512 * 64]);
        float act = __ldg(&g_ctxT[sb]);
        float aw  = __ldg(&g_wcsT[sb]);

        // ---- distributed wait: all producer flags must reach t ----
        if (t > 0) {
            bool ok;
            do {
                unsigned v = (tid < 128) ? ld_flag(myflag) : 0xffffffffu;
                ok = (v >= (unsigned)t);
            } while (!__syncthreads_and(ok));
        }

        const float* hb = (t == 0) ? g_h0T : (g_hT + (size_t)(t - 1) * (DIM * NB));
        const float4* hp = reinterpret_cast<const float4*>(hb) + hoff;

        ull acc2[2][5];
        #pragma unroll
        for (int p = 0; p < 2; p++)
            #pragma unroll
            for (int g = 0; g < 5; g++) acc2[p][g] = 0ull;

        #pragma unroll 16
        for (int i = 0; i < 128; i++) {
            float4 h4 = __ldg(hp + i * 16);
            ulonglong2 hv = *reinterpret_cast<ulonglong2*>(&h4);
            float4 wa = w4f[i * 2];
            float4 wb = w4f[i * 2 + 1];
            float2 wc = w1f[i];
            ull w0 = reinterpret_cast<ulonglong2*>(&wa)->x;
            ull w1 = reinterpret_cast<ulonglong2*>(&wa)->y;
            ull w2 = reinterpret_cast<ulonglong2*>(&wb)->x;
            ull w3 = reinterpret_cast<ulonglong2*>(&wb)->y;
            ull w4 = *reinterpret_cast<ull*>(&wc);
            ffma2(acc2[0][0], hv.x, w0);
            ffma2(acc2[0][1], hv.x, w1);
            ffma2(acc2[0][2], hv.x, w2);
            ffma2(acc2[0][3], hv.x, w3);
            ffma2(acc2[0][4], hv.x, w4);
            ffma2(acc2[1][0], hv.y, w0);
            ffma2(acc2[1][1], hv.y, w1);
            ffma2(acc2[1][2], hv.y, w2);
            ffma2(acc2[1][3], hv.y, w3);
            ffma2(acc2[1][4], hv.y, w4);
        }

        float a[20];
        #pragma unroll
        for (int p = 0; p < 2; p++)
            #pragma unroll
            for (int g = 0; g < 5; g++) {
                float2 v = *reinterpret_cast<float2*>(&acc2[p][g]);
                a[(2 * p + 0) * 5 + g] = v.x;
                a[(2 * p + 1) * 5 + g] = v.y;
            }

        #pragma unroll
        for (int q = 0; q < 20; q++) {
            a[q] += __shfl_xor_sync(0xffffffffu, a[q], 8);
            a[q] += __shfl_xor_sync(0xffffffffu, a[q], 16);
        }

        float fg  = sigmoid_fast(a[kc * 5 + 0] + af  + bf);
        float ig  = sigmoid_fast(a[kc * 5 + 1] + ai  + bi);
        float og  = sigmoid_fast(a[kc * 5 + 2] + ao  + bo);
        float ocg = sigmoid_fast(a[kc * 5 + 3] + aoc + boc);
        float ct  = tanh_fast   (a[kc * 5 + 4] + act + bfh);

        c_reg = ig * ct + fg * c_reg;
        float hv2 = og * tanh_fast(c_reg) + ocg * aw;

        g_hT[sb] = hv2;

        // ---- arrival: block's h stores visible, then bump this block's flag
        __syncthreads();
        if (tid == 0) {
            __threadfence();
            st_flag(&g_flags[blockIdx.x * 32], (unsigned)(t + 1));
        }
    }

    g_cT[(size_t)m * 64 + b_own] = c_reg;
}

// ---------------------------------------------------------------------------
// transpose g_hT [t][m][b] -> out [t][b][m]
// ---------------------------------------------------------------------------
__global__ void __launch_bounds__(256) transpose_kernel(float* __restrict__ out)
{
    __shared__ float tile[32][33];
    const int tx = threadIdx.x;       // 0..31
    const int ty = threadIdx.y;       // 0..7
    const int m0 = blockIdx.x * 32;
    const int b0 = blockIdx.y * 32;
    const int t  = blockIdx.z;

    const float* src = g_hT + (size_t)t * (512 * 64);
    #pragma unroll
    for (int k = 0; k < 4; k++)
        tile[ty + 8 * k][tx] = src[(size_t)(m0 + ty + 8 * k) * 64 + b0 + tx];
    __syncthreads();
    float* dst = out + (size_t)t * (64 * 512);
    #pragma unroll
    for (int k = 0; k < 4; k++)
        dst[(size_t)(b0 + ty + 8 * k) * 512 + m0 + tx] = tile[tx][ty + 8 * k];
}

__global__ void tail_kernel(float* __restrict__ out)
{
    int b = blockIdx.x;      // 64
    int m = threadIdx.x;     // 512
    out[TBM + (size_t)b * 512 + m]             = g_cT[(size_t)m * 64 + b];
    out[TBM + NB * DIM + (size_t)b * 512 + m]  = g_hT[(size_t)255 * (512 * 64) + (size_t)m * 64 + b];
}

// ---------------------------------------------------------------------------
extern "C" void kernel_launch(void* const* d_in, const int* in_sizes, int n_in,
                              void* d_out, int out_size)
{
    const float* inputs = (const float*)d_in[0];
    const float* emb_s  = (const float*)d_in[1];
    const float* c0     = (const float*)d_in[2];
    const float* h0     = (const float*)d_in[3];
    const float* W_ioux = (const float*)d_in[4];
    const float* b_ioux = (const float*)d_in[5];
    const float* W_iouh = (const float*)d_in[6];
    const float* b_iouh = (const float*)d_in[7];
    const float* W_ious = (const float*)d_in[8];
    const float* b_ious = (const float*)d_in[9];
    const float* W_fx   = (const float*)d_in[10];
    const float* b_fx   = (const float*)d_in[11];
    const float* W_fh   = (const float*)d_in[12];
    const float* b_fh   = (const float*)d_in[13];
    const float* W_wc   = (const float*)d_in[14];
    const float* b_wc   = (const float*)d_in[15];
    float* out = (float*)d_out;

    static int smem_set = 0;
    if (!smem_set) {
        cudaFuncSetAttribute(scan_kernel, cudaFuncAttributeMaxDynamicSharedMemorySize,
                             SCAN_SMEM_BYTES);
        smem_set = 1;
    }

    init_kernel<<<64, 512>>>(h0);
    gemm_kernel<<<dim3(16, 128), 256>>>(0, inputs, emb_s, W_ioux, W_ious,
                                        b_ioux, b_ious, 2048, 1024);
    gemm_kernel<<<dim3(4, 128), 256>>>(1, inputs, nullptr, W_fx, nullptr,
                                       b_fx, nullptr, 512, 512);
    gemm_kernel<<<dim3(4, 128), 256>>>(2, emb_s, nullptr, W_wc, nullptr,
                                       b_wc, nullptr, 512, 512);
    scan_kernel<<<128, 256, SCAN_SMEM_BYTES>>>(W_iouh, b_iouh, W_fh, b_fh, c0);
    transpose_kernel<<<dim3(16, 2, 256), dim3(32, 8)>>>(out);
    tail_kernel<<<64, 512>>>(out);
}

// round 5
// speedup vs baseline: 1.1774x; 1.1774x over previous
#include <cuda_runtime.h>
#include <math.h>

#define SEQ_T 256
#define NB    64
#define DIM   512
#define TBM   (SEQ_T * NB * DIM)   /* 8388608 */

// ---------------- scratch (static device memory; no runtime alloc) ----------
__device__ float g_iouT[(size_t)SEQ_T * 4 * DIM * NB];  // [t][gate][m][b]
__device__ float g_ctxT[(size_t)SEQ_T * DIM * NB];      // [t][m][b]
__device__ float g_wcsT[(size_t)SEQ_T * DIM * NB];      // [t][m][b]  (tanh applied)
__device__ float g_hT  [(size_t)SEQ_T * DIM * NB];      // [t][m][b]  h history (transposed)
__device__ float g_h0T [DIM * NB];                      // [m][b]
__device__ unsigned g_cnt;                              // grid-barrier counter

typedef unsigned long long ull;

__device__ __forceinline__ void ffma2(ull& d, ull a, ull b) {
    asm("fma.rn.f32x2 %0, %1, %2, %0;" : "+l"(d) : "l"(a), "l"(b));
}
__device__ __forceinline__ ull packdup(float a) {
    ull r; asm("mov.b64 %0, {%1, %1};" : "=l"(r) : "f"(a)); return r;
}
__device__ __forceinline__ float tanh_fast(float x) {
    float y; asm("tanh.approx.f32 %0, %1;" : "=f"(y) : "f"(x)); return y;
}
__device__ __forceinline__ float sigmoid_fast(float x) {
    return fmaf(0.5f, tanh_fast(0.5f * x), 0.5f);
}

// ---------------------------------------------------------------------------
__global__ void init_kernel(const float* __restrict__ h0) {
    int b = blockIdx.x;          // 64 blocks
    int m = threadIdx.x;         // 512 threads
    g_h0T[m * NB + b] = h0[b * DIM + m];
    if (b == 0 && m == 0) g_cnt = 0u;
}

// ---------------------------------------------------------------------------
// Fused fp32 SGEMM (FFMA2): all three projections in one launch.
//   blocks [0,2048)    : iou_x  (N=2048, K=1024 virtual concat)
//   blocks [2048,2560) : ctx    (N=512,  K=512)
//   blocks [2560,3072) : wcs    (N=512,  K=512, tanh epilogue)
// BM=BN=128, BK=16, 256 threads, 8x8 register tile (8x4 f32x2 pairs).
// ---------------------------------------------------------------------------
__global__ void __launch_bounds__(256) gemm_fused_kernel(
    const float* __restrict__ inputs, const float* __restrict__ emb_s,
    const float* __restrict__ W_ioux, const float* __restrict__ W_ious,
    const float* __restrict__ b_ioux, const float* __restrict__ b_ious,
    const float* __restrict__ W_fx,   const float* __restrict__ b_fx,
    const float* __restrict__ W_wc,   const float* __restrict__ b_wc)
{
    __shared__ float As[16 * 132];
    __shared__ float Bs[16 * 132];

    const int blk = blockIdx.x;
    int mode, bx, by, N, K;
    const float *A0, *A1, *B0, *B1, *bias0, *bias1;
    if (blk < 2048) {
        mode = 0; bx = blk & 15; by = blk >> 4; N = 2048; K = 1024;
        A0 = inputs; A1 = emb_s; B0 = W_ioux; B1 = W_ious; bias0 = b_ioux; bias1 = b_ious;
    } else if (blk < 2560) {
        int l = blk - 2048;
        mode = 1; bx = l & 3; by = l >> 2; N = 512; K = 512;
        A0 = inputs; A1 = nullptr; B0 = W_fx; B1 = nullptr; bias0 = b_fx; bias1 = nullptr;
    } else {
        int l = blk - 2560;
        mode = 2; bx = l & 3; by = l >> 2; N = 512; K = 512;
        A0 = emb_s; A1 = nullptr; B0 = W_wc; B1 = nullptr; bias0 = b_wc; bias1 = nullptr;
    }

    const int tid = threadIdx.x;
    const int bm  = by * 128;
    const int bn  = bx * 128;
    const int tx  = tid & 15;
    const int ty  = tid >> 4;

    ull accP[8][4];
    #pragma unroll
    for (int i = 0; i < 8; i++)
        #pragma unroll
        for (int j = 0; j < 4; j++) accP[i][j] = 0ull;

    for (int k0 = 0; k0 < K; k0 += 16) {
        const float* Asrc; const float* Bsrc; int ko;
        if (k0 < 512) { Asrc = A0; Bsrc = B0; ko = k0; }
        else          { Asrc = A1; Bsrc = B1; ko = k0 - 512; }

        #pragma unroll
        for (int i = 0; i < 2; i++) {
            int l  = tid + i * 256;
            int r  = l >> 2;
            int c4 = (l & 3) * 4;
            float4 av = *reinterpret_cast<const float4*>(Asrc + (size_t)(bm + r) * 512 + ko + c4);
            As[(c4 + 0) * 132 + r] = av.x;
            As[(c4 + 1) * 132 + r] = av.y;
            As[(c4 + 2) * 132 + r] = av.z;
            As[(c4 + 3) * 132 + r] = av.w;
            float4 bv = *reinterpret_cast<const float4*>(Bsrc + (size_t)(bn + r) * 512 + ko + c4);
            Bs[(c4 + 0) * 132 + r] = bv.x;
            Bs[(c4 + 1) * 132 + r] = bv.y;
            Bs[(c4 + 2) * 132 + r] = bv.z;
            Bs[(c4 + 3) * 132 + r] = bv.w;
        }
        __syncthreads();

        #pragma unroll
        for (int kk = 0; kk < 16; kk++) {
            float a8[8];
            float4 b0 = *reinterpret_cast<const float4*>(&Bs[kk * 132 + tx * 8]);
            float4 b1 = *reinterpret_cast<const float4*>(&Bs[kk * 132 + tx * 8 + 4]);
            *reinterpret_cast<float4*>(a8)     = *reinterpret_cast<const float4*>(&As[kk * 132 + ty * 8]);
            *reinterpret_cast<float4*>(a8 + 4) = *reinterpret_cast<const float4*>(&As[kk * 132 + ty * 8 + 4]);
            ull bp[4];
            bp[0] = reinterpret_cast<const ulonglong2*>(&b0)->x;
            bp[1] = reinterpret_cast<const ulonglong2*>(&b0)->y;
            bp[2] = reinterpret_cast<const ulonglong2*>(&b1)->x;
            bp[3] = reinterpret_cast<const ulonglong2*>(&b1)->y;
            #pragma unroll
            for (int i = 0; i < 8; i++) {
                ull ad = packdup(a8[i]);
                #pragma unroll
                for (int j = 0; j < 4; j++)
                    ffma2(accP[i][j], ad, bp[j]);
            }
        }
        __syncthreads();
    }

    const int col0 = bn + tx * 8;
    float bias[8];
    #pragma unroll
    for (int j = 0; j < 8; j++) {
        float v = bias0[col0 + j];
        if (bias1) v += bias1[col0 + j];
        bias[j] = v;
    }

    #pragma unroll
    for (int i = 0; i < 8; i++) {
        int row = bm + ty * 8 + i;
        int t   = row >> 6;
        int b   = row & 63;
        #pragma unroll
        for (int j = 0; j < 8; j++) {
            float2 pr = *reinterpret_cast<float2*>(&accP[i][j >> 1]);
            float v = ((j & 1) ? pr.y : pr.x) + bias[j];
            int col = col0 + j;
            if (mode == 0) {
                int g  = col >> 9;
                int mc = col & 511;
                g_iouT[(((size_t)t * 4 + g) * 512 + mc) * 64 + b] = v;
            } else if (mode == 1) {
                g_ctxT[(size_t)t * (512 * 64) + (size_t)col * 64 + b] = v;
            } else {
                g_wcsT[(size_t)t * (512 * 64) + (size_t)col * 64 + b] = tanhf(v);
            }
        }
    }
}

// ---------------------------------------------------------------------------
// Persistent weight-stationary scan with FFMA2 (R3 barrier). 128 blocks,
// 256 threads. Weights duplicated (w,w) in ~80KB dynamic smem.
// Writes g_hT [t][m][b] (next-step broadcast) AND out [t][b][m] + tails.
// ---------------------------------------------------------------------------
#define W4TOT 16448                       /* floats: 4 m * (4 kc * 1028) */
#define SCAN_SMEM_FLOATS (W4TOT + 4 * 1032)
#define SCAN_SMEM_BYTES  (SCAN_SMEM_FLOATS * 4)

__global__ void __launch_bounds__(256) scan_kernel(
    const float* __restrict__ W_iouh, const float* __restrict__ b_iouh,
    const float* __restrict__ W_fh,   const float* __restrict__ b_fh,
    const float* __restrict__ c0,     float* __restrict__ out)
{
    extern __shared__ float sm[];

    const int tid   = threadIdx.x;
    const int warp  = tid >> 5;
    const int lane  = tid & 31;
    const int m_l   = warp >> 1;
    const int bhalf = warp & 1;
    const int kc    = (lane >> 3) & 3;
    const int bq    = lane & 7;
    const int m     = blockIdx.x * 4 + m_l;
    const int b_own = bhalf * 32 + bq * 4 + kc;

    // ---- weights into smem, duplicated (w,w) pairs ----
    for (int idx = tid; idx < 8192; idx += 256) {
        int ml = idx >> 11;
        int r  = idx & 2047;
        int c  = r >> 9;
        int r2 = r & 511;
        int i  = r2 >> 2;
        int g  = r2 & 3;
        int mg = blockIdx.x * 4 + ml;
        float w = W_iouh[((size_t)g * 512 + mg) * 512 + c * 128 + i];
        float* p = sm + ml * 4112 + c * 1028 + i * 8 + g * 2;
        p[0] = w; p[1] = w;
    }
    for (int idx = tid; idx < 2048; idx += 256) {
        int ml = idx >> 9;
        int r  = idx & 511;
        int c  = r >> 7;
        int i  = r & 127;
        int mg = blockIdx.x * 4 + ml;
        float w = W_fh[(size_t)mg * 512 + c * 128 + i];
        float* p = sm + W4TOT + ml * 1032 + c * 258 + i * 2;
        p[0] = w; p[1] = w;
    }
    __syncthreads();

    const float bf  = b_iouh[m];
    const float bi  = b_iouh[512 + m];
    const float bo  = b_iouh[1024 + m];
    const float boc = b_iouh[1536 + m];
    const float bfh = b_fh[m];

    float c_reg = c0[(size_t)b_own * 512 + m];
    float hv2 = 0.f;

    const float4* w4f = reinterpret_cast<const float4*>(sm + m_l * 4112 + kc * 1028);
    const float2* w1f = reinterpret_cast<const float2*>(sm + W4TOT + m_l * 1032 + kc * 258);
    const int hoff = kc * 2048 + bhalf * 8 + bq;   // float4 index within step slice

    for (int t = 0; t < SEQ_T; t++) {
        const float* hb = (t == 0) ? g_h0T : (g_hT + (size_t)(t - 1) * (DIM * NB));
        const float4* hp = reinterpret_cast<const float4*>(hb) + hoff;

        // addend loads (independent of h); L2 latency hides under inner loop
        const size_t ib = (((size_t)t * 4) * 512 + m) * 64 + b_own;
        const size_t sb = (size_t)t * (512 * 64) + (size_t)m * 64 + b_own;
        float af  = __ldg(&g_iouT[ib]);
        float ai  = __ldg(&g_iouT[ib + 1 * 512 * 64]);
        float ao  = __ldg(&g_iouT[ib + 2 * 512 * 64]);
        float aoc = __ldg(&g_iouT[ib + 3 * 512 * 64]);
        float act = __ldg(&g_ctxT[sb]);
        float aw  = __ldg(&g_wcsT[sb]);

        ull acc2[2][5];
        #pragma unroll
        for (int p = 0; p < 2; p++)
            #pragma unroll
            for (int g = 0; g < 5; g++) acc2[p][g] = 0ull;

        #pragma unroll 8
        for (int i = 0; i < 128; i++) {
            float4 h4 = __ldg(hp + i * 16);
            ulonglong2 hv = *reinterpret_cast<ulonglong2*>(&h4);
            float4 wa = w4f[i * 2];
            float4 wb = w4f[i * 2 + 1];
            float2 wc = w1f[i];
            ull w0 = reinterpret_cast<ulonglong2*>(&wa)->x;
            ull w1 = reinterpret_cast<ulonglong2*>(&wa)->y;
            ull w2 = reinterpret_cast<ulonglong2*>(&wb)->x;
            ull w3 = reinterpret_cast<ulonglong2*>(&wb)->y;
            ull w4 = *reinterpret_cast<ull*>(&wc);
            ffma2(acc2[0][0], hv.x, w0);
            ffma2(acc2[0][1], hv.x, w1);
            ffma2(acc2[0][2], hv.x, w2);
            ffma2(acc2[0][3], hv.x, w3);
            ffma2(acc2[0][4], hv.x, w4);
            ffma2(acc2[1][0], hv.y, w0);
            ffma2(acc2[1][1], hv.y, w1);
            ffma2(acc2[1][2], hv.y, w2);
            ffma2(acc2[1][3], hv.y, w3);
            ffma2(acc2[1][4], hv.y, w4);
        }

        float a[20];
        #pragma unroll
        for (int p = 0; p < 2; p++)
            #pragma unroll
            for (int g = 0; g < 5; g++) {
                float2 v = *reinterpret_cast<float2*>(&acc2[p][g]);
                a[(2 * p + 0) * 5 + g] = v.x;
                a[(2 * p + 1) * 5 + g] = v.y;
            }

        #pragma unroll
        for (int q = 0; q < 20; q++) {
            a[q] += __shfl_xor_sync(0xffffffffu, a[q], 8);
            a[q] += __shfl_xor_sync(0xffffffffu, a[q], 16);
        }

        float fg  = sigmoid_fast(a[kc * 5 + 0] + af  + bf);
        float ig  = sigmoid_fast(a[kc * 5 + 1] + ai  + bi);
        float og  = sigmoid_fast(a[kc * 5 + 2] + ao  + bo);
        float ocg = sigmoid_fast(a[kc * 5 + 3] + aoc + boc);
        float ct  = tanh_fast   (a[kc * 5 + 4] + act + bfh);

        c_reg = ig * ct + fg * c_reg;
        hv2 = og * tanh_fast(c_reg) + ocg * aw;

        g_hT[sb] = hv2;                                          // [t][m][b]
        out[(size_t)t * (NB * DIM) + (size_t)b_own * 512 + m] = hv2;  // [t][b][m]

        // ---- grid barrier (R3): bar.sync, elected thread fence+arrive+spin
        __syncthreads();
        if (tid == 0) {
            __threadfence();
            atomicAdd(&g_cnt, 1u);
            const unsigned target = (unsigned)gridDim.x * (unsigned)(t + 1);
            while (*reinterpret_cast<volatile unsigned*>(&g_cnt) < target) { }
            __threadfence();
        }
        __syncthreads();
    }

    // tails
    out[TBM + (size_t)b_own * 512 + m]            = c_reg;
    out[TBM + NB * DIM + (size_t)b_own * 512 + m] = hv2;
}

// ---------------------------------------------------------------------------
extern "C" void kernel_launch(void* const* d_in, const int* in_sizes, int n_in,
                              void* d_out, int out_size)
{
    const float* inputs = (const float*)d_in[0];
    const float* emb_s  = (const float*)d_in[1];
    const float* c0     = (const float*)d_in[2];
    const float* h0     = (const float*)d_in[3];
    const float* W_ioux = (const float*)d_in[4];
    const float* b_ioux = (const float*)d_in[5];
    const float* W_iouh = (const float*)d_in[6];
    const float* b_iouh = (const float*)d_in[7];
    const float* W_ious = (const float*)d_in[8];
    const float* b_ious = (const float*)d_in[9];
    const float* W_fx   = (const float*)d_in[10];
    const float* b_fx   = (const float*)d_in[11];
    const float* W_fh   = (const float*)d_in[12];
    const float* b_fh   = (const float*)d_in[13];
    const float* W_wc   = (const float*)d_in[14];
    const float* b_wc   = (const float*)d_in[15];
    float* out = (float*)d_out;

    static int smem_set = 0;
    if (!smem_set) {
        cudaFuncSetAttribute(scan_kernel, cudaFuncAttributeMaxDynamicSharedMemorySize,
                             SCAN_SMEM_BYTES);
        smem_set = 1;
    }

    init_kernel<<<64, 512>>>(h0);
    gemm_fused_kernel<<<3072, 256>>>(inputs, emb_s, W_ioux, W_ious, b_ioux, b_ious,
                                     W_fx, b_fx, W_wc, b_wc);
    scan_kernel<<<128, 256, SCAN_SMEM_BYTES>>>(W_iouh, b_iouh, W_fh, b_fh, c0, out);
}